// round 13
// baseline (speedup 1.0000x reference)
#include <cuda_runtime.h>
#include <cuda_fp16.h>
#include <cstdint>

#define T_TOK 4096
#define DDIM  1024
#define FDIM  2048
#define NEXP  8
#define BM 128
#define BN 128

// ------------------- static device scratch -------------------
// fragment-packed operands:
// A packs: per (row-atom of 16 rows) x (k-atom of 16 cols): 32 lanes x 16B (256 halves)
// B packs: per (n-atom of 8 rows) x (k-atom of 16 cols):    32 lanes x  8B (128 halves)
__device__ __align__(16) __half g_xp  [(size_t)(NEXP+1)*T_TOK*DDIM];                  // packed A for up (75MB)
__device__ __align__(16) __half g_hp  [(size_t)(NEXP+1)*T_TOK*FDIM];                  // packed A for down (151MB)
__device__ __align__(16) __half g_wupP[(size_t)(NEXP+1)*(FDIM/8)*(DDIM/16)*128];      // packed B up (38MB)
__device__ __align__(16) __half g_wdnP[(size_t)(NEXP+1)*(DDIM/8)*(FDIM/16)*128];      // packed B down (38MB)
__device__ __align__(16) float  g_yr  [(size_t)NEXP*T_TOK*DDIM];                      // routed down out (by slot)
__device__ int   g_cnt[NEXP];
__device__ int   g_idx[NEXP*T_TOK];
__device__ int   g_te[2*T_TOK];
__device__ int   g_ts[2*T_TOK];
__device__ float g_tw[2*T_TOK];

// ------------------- pre-main side stream/events -------------------
struct SideInit {
  cudaStream_t s;
  cudaEvent_t  ef, er, ej;
  SideInit(){
    cudaStreamCreateWithFlags(&s, cudaStreamNonBlocking);
    cudaEventCreateWithFlags(&ef, cudaEventDisableTiming);
    cudaEventCreateWithFlags(&er, cudaEventDisableTiming);
    cudaEventCreateWithFlags(&ej, cudaEventDisableTiming);
  }
};
static SideInit g_side;

// ------------------------------- helpers -------------------------------
__device__ __forceinline__ void mma16816(float* c, const uint32_t* a, const uint32_t* b){
  asm volatile("mma.sync.aligned.m16n8k16.row.col.f32.f16.f16.f32 "
    "{%0,%1,%2,%3}, {%4,%5,%6,%7}, {%8,%9}, {%0,%1,%2,%3};\n"
    : "+f"(c[0]),"+f"(c[1]),"+f"(c[2]),"+f"(c[3])
    : "r"(a[0]),"r"(a[1]),"r"(a[2]),"r"(a[3]), "r"(b[0]),"r"(b[1]));
}

// ------------------------------- weight pack: fp32 [rows][K] -> B-fragment packs -------------------------------
// layout: [row-atom na (8 rows)][k-atom ka][lane]{8B = w[n][k0..k1], w[n][k8..k9]}
// with n = na*8 + (lane>>2), k = ka*16 + (lane&3)*2
__global__ void pack_w(const float* __restrict__ w, __half* __restrict__ dst, int K, int nka){
  const int na = blockIdx.x;
  const int warp = threadIdx.x >> 5, lane = threadIdx.x & 31;
  const float* wr = w + ((size_t)na*8 + (lane>>2))*K + (lane&3)*2;
  __half* db = dst + (size_t)na*nka*128 + lane*4;
  for (int ka = warp; ka < nka; ka += 4){
    const float* s = wr + ka*16;
    float2 v0 = *(const float2*)(s);
    float2 v1 = *(const float2*)(s + 8);
    uint2 o;
    reinterpret_cast<__half2*>(&o)[0] = __floats2half2_rn(v0.x, v0.y);
    reinterpret_cast<__half2*>(&o)[1] = __floats2half2_rn(v1.x, v1.y);
    *reinterpret_cast<uint2*>(db + (size_t)ka*128) = o;
  }
}

// ------------------------------- x pack: gather + fp16 + A-fragment layout -------------------------------
// layout: [expert e][row-atom ma (16 rows)][k-atom ka][lane]{16B = x[r0][k0k1], x[r1][k0k1], x[r0][k8k9], x[r1][k8k9]}
// with r0 = ma*16 + (lane>>2), r1 = r0+8, k = ka*16 + (lane&3)*2
__global__ void pack_x(const float* __restrict__ x){
  const int e = blockIdx.z, ma = blockIdx.x;
  const int warp = threadIdx.x >> 5, lane = threadIdx.x & 31;
  const int cnt = (e < NEXP) ? g_cnt[e] : T_TOK;
  if (ma*16 >= cnt) return;
  int r0 = ma*16 + (lane>>2), r1 = r0 + 8;
  int t0, t1;
  if (e < NEXP){
    const int* idx = &g_idx[e*T_TOK];
    t0 = (r0 < cnt) ? idx[r0] : idx[cnt-1];
    t1 = (r1 < cnt) ? idx[r1] : idx[cnt-1];
  } else { t0 = r0; t1 = r1; }
  const float* x0 = x + (size_t)t0*DDIM + (lane&3)*2;
  const float* x1 = x + (size_t)t1*DDIM + (lane&3)*2;
  __half* db = g_xp + (((size_t)e*(T_TOK/16) + ma)*(DDIM/16))*256 + lane*8;
  for (int ka = warp; ka < DDIM/16; ka += 8){
    float2 a0 = *(const float2*)(x0 + ka*16);
    float2 b0 = *(const float2*)(x1 + ka*16);
    float2 a1 = *(const float2*)(x0 + ka*16 + 8);
    float2 b1 = *(const float2*)(x1 + ka*16 + 8);
    uint4 o;
    reinterpret_cast<__half2*>(&o)[0] = __floats2half2_rn(a0.x, a0.y);
    reinterpret_cast<__half2*>(&o)[1] = __floats2half2_rn(b0.x, b0.y);
    reinterpret_cast<__half2*>(&o)[2] = __floats2half2_rn(a1.x, a1.y);
    reinterpret_cast<__half2*>(&o)[3] = __floats2half2_rn(b1.x, b1.y);
    *reinterpret_cast<uint4*>(db + (size_t)ka*256) = o;
  }
}

// ------------------------------- router -------------------------------
__global__ void router_kernel(const float* __restrict__ x,
                              const float* __restrict__ rw,
                              const float* __restrict__ rb){
  const int t = blockIdx.x;
  const int warp = threadIdx.x >> 5, lane = threadIdx.x & 31;
  const float4* xr = reinterpret_cast<const float4*>(x + (size_t)t*DDIM);
  const float4* wr = reinterpret_cast<const float4*>(rw + (size_t)warp*DDIM);
  float acc = 0.f;
#pragma unroll
  for (int i=0;i<DDIM/128;i++){
    float4 a = xr[lane + i*32], b = wr[lane + i*32];
    acc += a.x*b.x + a.y*b.y + a.z*b.z + a.w*b.w;
  }
#pragma unroll
  for (int o=16;o;o>>=1) acc += __shfl_xor_sync(0xffffffffu, acc, o);
  __shared__ float lg[NEXP];
  if (lane==0) lg[warp] = acc + rb[warp];
  __syncthreads();
  if (threadIdx.x==0){
    int i0=0; float v0=lg[0];
#pragma unroll
    for (int e=1;e<NEXP;e++) if (lg[e] > v0){ v0=lg[e]; i0=e; }
    int i1=-1; float v1=-3.4e38f;
#pragma unroll
    for (int e=0;e<NEXP;e++) if (e!=i0 && lg[e] > v1){ v1=lg[e]; i1=e; }
    float w0 = 1.f/(1.f + expf(v1 - v0));
    float w1 = 1.f - w0;
    int s0 = atomicAdd(&g_cnt[i0],1);
    g_idx[i0*T_TOK+s0] = t;
    int s1 = atomicAdd(&g_cnt[i1],1);
    g_idx[i1*T_TOK+s1] = t;
    g_te[2*t]=i0; g_te[2*t+1]=i1;
    g_ts[2*t]=s0; g_ts[2*t+1]=s1;
    g_tw[2*t]=w0; g_tw[2*t+1]=w1;
  }
}

// ------------------------------- smem-free fragment GEMM -------------------------------
// 128x128 block, 4 warps (2x2), 64x64 warp tile. Operands loaded as fragments via LDG.
// UP=1: g_xp @ w_upP -> silu -> packed store to g_hp
// UP=0: g_hp @ w_dnP -> fp32 rows (e<8 -> g_yr by slot, e==8 -> out)
template<int UP>
__global__ __launch_bounds__(128, 2)
void moe_gemm4(float* __restrict__ gout){
  constexpr int KD  = UP ? DDIM : FDIM;
  constexpr int ND  = UP ? FDIM : DDIM;
  constexpr int NKA = KD/16;
  const int e = blockIdx.z;
  const int nrows = (e < NEXP) ? g_cnt[e] : T_TOK;
  const int m0 = blockIdx.x*BM;
  if (m0 >= nrows) return;
  const int n0 = blockIdx.y*BN;
  const int lane = threadIdx.x & 31, warp = threadIdx.x >> 5;
  const int wm = (warp & 1)*64, wn = (warp >> 1)*64;

  const __half* Ap = (UP ? g_xp : g_hp) + (size_t)e*(T_TOK/16)*(size_t)NKA*256;
  const __half* Bp = (UP ? g_wupP : g_wdnP) + (size_t)e*(ND/8)*(size_t)NKA*128;

  const __half* Ar[4];
#pragma unroll
  for (int mi=0;mi<4;mi++)
    Ar[mi] = Ap + (size_t)((m0+wm)/16 + mi)*NKA*256 + lane*8;
  const __half* Br[8];
#pragma unroll
  for (int nj=0;nj<8;nj++)
    Br[nj] = Bp + (size_t)((n0+wn)/8 + nj)*NKA*128 + lane*4;

  float acc[4][8][4];
#pragma unroll
  for (int a=0;a<4;a++)
#pragma unroll
    for (int b=0;b<8;b++)
#pragma unroll
      for (int r=0;r<4;r++) acc[a][b][r]=0.f;

  uint4 afr[2][4];
  uint2 bfr[2][8];
#pragma unroll
  for (int mi=0;mi<4;mi++) afr[0][mi] = *reinterpret_cast<const uint4*>(Ar[mi]);
#pragma unroll
  for (int nj=0;nj<8;nj++) bfr[0][nj] = *reinterpret_cast<const uint2*>(Br[nj]);

  for (int ka=0; ka<NKA; ++ka){
    int cur = ka & 1;
    if (ka+1 < NKA){
#pragma unroll
      for (int mi=0;mi<4;mi++)
        afr[cur^1][mi] = *reinterpret_cast<const uint4*>(Ar[mi] + (size_t)(ka+1)*256);
#pragma unroll
      for (int nj=0;nj<8;nj++)
        bfr[cur^1][nj] = *reinterpret_cast<const uint2*>(Br[nj] + (size_t)(ka+1)*128);
    }
#pragma unroll
    for (int mi=0;mi<4;mi++)
#pragma unroll
      for (int ni=0;ni<8;ni++)
        mma16816(acc[mi][ni],
                 reinterpret_cast<const uint32_t*>(&afr[cur][mi]),
                 reinterpret_cast<const uint32_t*>(&bfr[cur][ni]));
  }

  // ------------------------------- epilogue -------------------------------
  if constexpr (UP){
    // silu + store as packed A-fragments for the down GEMM (no row guard: garbage rows discarded there)
    __half* Hb = g_hp + (size_t)e*(T_TOK/16)*(FDIM/16)*256;
#pragma unroll
    for (int mi=0;mi<4;mi++){
      __half* rowp = Hb + (size_t)((m0+wm)/16 + mi)*(FDIM/16)*256 + lane*8;
#pragma unroll
      for (int j=0;j<4;j++){
        int ka = (n0+wn)/16 + j;
        float v[4][2];
#pragma unroll
        for (int q=0;q<2;q++){        // q: ni even/odd within the k-atom
#pragma unroll
          for (int rr=0;rr<2;rr++){
            float s0 = acc[mi][2*j+q][rr*2+0];
            float s1 = acc[mi][2*j+q][rr*2+1];
            v[q*2+rr][0] = s0 / (1.f + __expf(-s0));
            v[q*2+rr][1] = s1 / (1.f + __expf(-s1));
          }
        }
        uint4 o;
        reinterpret_cast<__half2*>(&o)[0] = __floats2half2_rn(v[0][0], v[0][1]); // r0, k0k1
        reinterpret_cast<__half2*>(&o)[1] = __floats2half2_rn(v[1][0], v[1][1]); // r1, k0k1
        reinterpret_cast<__half2*>(&o)[2] = __floats2half2_rn(v[2][0], v[2][1]); // r0, k8k9
        reinterpret_cast<__half2*>(&o)[3] = __floats2half2_rn(v[3][0], v[3][1]); // r1, k8k9
        *reinterpret_cast<uint4*>(rowp + (size_t)ka*256) = o;
      }
    }
  } else {
    float* Yout = (e < NEXP) ? (g_yr + (size_t)e*T_TOK*DDIM) : gout;
    const int gr = lane >> 2, gc = (lane & 3)*2;
#pragma unroll
    for (int mi=0;mi<4;mi++){
#pragma unroll
      for (int rr=0;rr<2;rr++){
        int m = m0 + wm + mi*16 + gr + rr*8;
        if (m < nrows){
          float* dst = &Yout[(size_t)m*ND + n0 + wn];
#pragma unroll
          for (int ni=0;ni<8;ni++){
            float2 f = make_float2(acc[mi][ni][rr*2+0], acc[mi][ni][rr*2+1]);
            *reinterpret_cast<float2*>(dst + ni*8 + gc) = f;
          }
        }
      }
    }
  }
}

// ------------------------------- combine -------------------------------
__global__ void combine_kernel(float* __restrict__ out){
  const int t = blockIdx.x;
  const int e0 = g_te[2*t], e1 = g_te[2*t+1];
  const int s0 = g_ts[2*t], s1 = g_ts[2*t+1];
  const float w0 = g_tw[2*t], w1 = g_tw[2*t+1];
  const float4* y0 = reinterpret_cast<const float4*>(&g_yr[((size_t)e0*T_TOK + s0)*DDIM]);
  const float4* y1 = reinterpret_cast<const float4*>(&g_yr[((size_t)e1*T_TOK + s1)*DDIM]);
  float4* o = reinterpret_cast<float4*>(out + (size_t)t*DDIM);
  const int i = threadIdx.x;
  float4 a = o[i], b = y0[i], c = y1[i];
  a.x += w0*b.x + w1*c.x;
  a.y += w0*b.y + w1*c.y;
  a.z += w0*b.z + w1*c.z;
  a.w += w0*b.w + w1*c.w;
  o[i] = a;
}

// ------------------------------- launch (fork-join graph) -------------------------------
extern "C" void kernel_launch(void* const* d_in, const int* in_sizes, int n_in,
                              void* d_out, int out_size){
  const float* x   = (const float*)d_in[0];
  const float* rw  = (const float*)d_in[1];
  const float* rb  = (const float*)d_in[2];
  const float* wup = (const float*)d_in[3];
  const float* wdn = (const float*)d_in[4];
  const float* swu = (const float*)d_in[5];
  const float* swd = (const float*)d_in[6];
  float* out = (float*)d_out;

  void *pcnt, *pwuP, *pwdP;
  cudaGetSymbolAddress(&pcnt, g_cnt);
  cudaGetSymbolAddress(&pwuP, g_wupP);
  cudaGetSymbolAddress(&pwdP, g_wdnP);
  __half* wupP = (__half*)pwuP;
  __half* wdnP = (__half*)pwdP;

  // fork
  cudaEventRecord(g_side.ef, 0);
  cudaStreamWaitEvent(g_side.s, g_side.ef, 0);

  // side branch: router -> x pack (gathered, per expert) -> down-weight packs
  cudaMemsetAsync(pcnt, 0, NEXP*sizeof(int), g_side.s);
  router_kernel<<<T_TOK, 256, 0, g_side.s>>>(x, rw, rb);
  pack_x<<<dim3(T_TOK/16, 1, NEXP+1), 256, 0, g_side.s>>>(x);
  cudaEventRecord(g_side.er, g_side.s);
  pack_w<<<NEXP*(DDIM/8), 128, 0, g_side.s>>>(wdn, wdnP, FDIM, FDIM/16);
  pack_w<<<DDIM/8, 128, 0, g_side.s>>>(swd, wdnP + (size_t)NEXP*(DDIM/8)*(FDIM/16)*128, FDIM, FDIM/16);
  cudaEventRecord(g_side.ej, g_side.s);

  // main branch: up-weight packs
  pack_w<<<NEXP*(FDIM/8), 128>>>(wup, wupP, DDIM, DDIM/16);
  pack_w<<<FDIM/8, 128>>>(swu, wupP + (size_t)NEXP*(FDIM/8)*(DDIM/16)*128, DDIM, DDIM/16);

  // join: x packs ready -> up-GEMM
  cudaStreamWaitEvent(0, g_side.er, 0);
  moe_gemm4<1><<<dim3(T_TOK/BM, FDIM/BN, NEXP+1), 128>>>(out);

  // join: down-weight packs ready -> down-GEMM
  cudaStreamWaitEvent(0, g_side.ej, 0);
  moe_gemm4<0><<<dim3(T_TOK/BM, DDIM/BN, NEXP+1), 128>>>(out);
  combine_kernel<<<T_TOK, 256>>>(out);
}

// round 14
// speedup vs baseline: 1.2498x; 1.2498x over previous
#include <cuda_runtime.h>
#include <cuda_fp16.h>
#include <cstdint>

#define T_TOK 4096
#define DDIM  1024
#define FDIM  2048
#define NEXP  8
#define BM 128
#define BN 128
#define BK 64
#define NST 3
#define STAGE (BM*128 + BN*128)          /* 32 KB per stage */
#define SMEM_DYN (NST*STAGE + 128)

// ------------------- static device scratch -------------------
__device__ __align__(16) __half g_xh [(size_t)T_TOK*DDIM];
__device__ __align__(16) __half g_wup[(size_t)NEXP*FDIM*DDIM];
__device__ __align__(16) __half g_wdn[(size_t)NEXP*DDIM*FDIM];
__device__ __align__(16) __half g_swu[(size_t)FDIM*DDIM];
__device__ __align__(16) __half g_swd[(size_t)DDIM*FDIM];
__device__ __align__(16) __half g_h  [(size_t)NEXP*T_TOK*FDIM];
__device__ __align__(16) __half g_hs [(size_t)T_TOK*FDIM];
__device__ __align__(16) float  g_yr [(size_t)NEXP*T_TOK*DDIM];
__device__ int   g_cnt[NEXP];
__device__ int   g_idx[NEXP*T_TOK];
__device__ int   g_te[2*T_TOK];
__device__ int   g_ts[2*T_TOK];
__device__ float g_tw[2*T_TOK];

// ------------------- pre-main streams/events (host objects only) -------------------
#define NCHAIN (NEXP+1)
struct SideInit {
  cudaStream_t sa, sb, sr, sc;         // converts + router
  cudaStream_t se[NCHAIN];             // per-expert chains
  cudaEvent_t  ef, e_x, e_wu, e_su, e_r, e_wd, e_done[NCHAIN];
  SideInit(){
    cudaStreamCreateWithFlags(&sa, cudaStreamNonBlocking);
    cudaStreamCreateWithFlags(&sb, cudaStreamNonBlocking);
    cudaStreamCreateWithFlags(&sr, cudaStreamNonBlocking);
    cudaStreamCreateWithFlags(&sc, cudaStreamNonBlocking);
    for (int i=0;i<NCHAIN;i++) cudaStreamCreateWithFlags(&se[i], cudaStreamNonBlocking);
    cudaEventCreateWithFlags(&ef,  cudaEventDisableTiming);
    cudaEventCreateWithFlags(&e_x, cudaEventDisableTiming);
    cudaEventCreateWithFlags(&e_wu,cudaEventDisableTiming);
    cudaEventCreateWithFlags(&e_su,cudaEventDisableTiming);
    cudaEventCreateWithFlags(&e_r, cudaEventDisableTiming);
    cudaEventCreateWithFlags(&e_wd,cudaEventDisableTiming);
    for (int i=0;i<NCHAIN;i++) cudaEventCreateWithFlags(&e_done[i], cudaEventDisableTiming);
  }
};
static SideInit g_side;

// ------------------------------- helpers -------------------------------
__device__ __forceinline__ uint32_t smem_u32(const void* p){
  uint32_t a;
  asm("{ .reg .u64 t; cvta.to.shared.u64 t, %1; cvt.u32.u64 %0, t; }" : "=r"(a) : "l"(p));
  return a;
}
__device__ __forceinline__ void cp16s(uint32_t sa, const void* g){
  asm volatile("cp.async.cg.shared.global [%0], [%1], 16;\n" :: "r"(sa), "l"(g));
}
__device__ __forceinline__ void cp_commit(){ asm volatile("cp.async.commit_group;\n"); }
template<int N> __device__ __forceinline__ void cp_wait(){
  asm volatile("cp.async.wait_group %0;\n" :: "n"(N));
}
__device__ __forceinline__ void ldsm4(uint32_t* r, uint32_t a){
  asm volatile("ldmatrix.sync.aligned.m8n8.x4.shared.b16 {%0,%1,%2,%3}, [%4];\n"
    : "=r"(r[0]),"=r"(r[1]),"=r"(r[2]),"=r"(r[3]) : "r"(a));
}
__device__ __forceinline__ void mma16816(float* c, const uint32_t* a, const uint32_t* b){
  asm volatile("mma.sync.aligned.m16n8k16.row.col.f32.f16.f16.f32 "
    "{%0,%1,%2,%3}, {%4,%5,%6,%7}, {%8,%9}, {%0,%1,%2,%3};\n"
    : "+f"(c[0]),"+f"(c[1]),"+f"(c[2]),"+f"(c[3])
    : "r"(a[0]),"r"(a[1]),"r"(a[2]),"r"(a[3]), "r"(b[0]),"r"(b[1]));
}

// ------------------------------- fp32 -> fp16 convert (ILP-4 streaming) -------------------------------
__global__ void f2h_kernel(const float4* __restrict__ s, uint2* __restrict__ d, int n4){
  int i0 = blockIdx.x*(blockDim.x*4) + threadIdx.x;
  float4 v[4];
#pragma unroll
  for (int u=0;u<4;u++){
    int i = i0 + u*blockDim.x;
    if (i < n4) v[u] = s[i];
  }
#pragma unroll
  for (int u=0;u<4;u++){
    int i = i0 + u*blockDim.x;
    if (i < n4){
      __half2 h0 = __floats2half2_rn(v[u].x, v[u].y);
      __half2 h1 = __floats2half2_rn(v[u].z, v[u].w);
      uint2 o;
      o.x = *reinterpret_cast<uint32_t*>(&h0);
      o.y = *reinterpret_cast<uint32_t*>(&h1);
      d[i] = o;
    }
  }
}

// ------------------------------- router -------------------------------
__global__ void router_kernel(const float* __restrict__ x,
                              const float* __restrict__ rw,
                              const float* __restrict__ rb){
  const int t = blockIdx.x;
  const int warp = threadIdx.x >> 5, lane = threadIdx.x & 31;
  const float4* xr = reinterpret_cast<const float4*>(x + (size_t)t*DDIM);
  const float4* wr = reinterpret_cast<const float4*>(rw + (size_t)warp*DDIM);
  float acc = 0.f;
#pragma unroll
  for (int i=0;i<DDIM/128;i++){
    float4 a = xr[lane + i*32], b = wr[lane + i*32];
    acc += a.x*b.x + a.y*b.y + a.z*b.z + a.w*b.w;
  }
#pragma unroll
  for (int o=16;o;o>>=1) acc += __shfl_xor_sync(0xffffffffu, acc, o);
  __shared__ float lg[NEXP];
  if (lane==0) lg[warp] = acc + rb[warp];
  __syncthreads();
  if (threadIdx.x==0){
    int i0=0; float v0=lg[0];
#pragma unroll
    for (int e=1;e<NEXP;e++) if (lg[e] > v0){ v0=lg[e]; i0=e; }
    int i1=-1; float v1=-3.4e38f;
#pragma unroll
    for (int e=0;e<NEXP;e++) if (e!=i0 && lg[e] > v1){ v1=lg[e]; i1=e; }
    float w0 = 1.f/(1.f + expf(v1 - v0));
    float w1 = 1.f - w0;
    int s0 = atomicAdd(&g_cnt[i0],1);
    g_idx[i0*T_TOK+s0] = t;
    int s1 = atomicAdd(&g_cnt[i1],1);
    g_idx[i1*T_TOK+s1] = t;
    g_te[2*t]=i0; g_te[2*t+1]=i1;
    g_ts[2*t]=s0; g_ts[2*t+1]=s1;
    g_tw[2*t]=w0; g_tw[2*t+1]=w1;
  }
}

// ------------------------------- grouped GEMM (R9 config; expert passed as arg) -------------------------------
template<int UP>
__global__ __launch_bounds__(128, 2)
void moe_gemm2(float* __restrict__ gout, int e){
  constexpr int KD = UP ? DDIM : FDIM;
  constexpr int ND = UP ? FDIM : DDIM;
  constexpr int KT = KD / BK;

  int nrows; const __half* A; const __half* Bp;
  const int* gidx = nullptr; __half* Hc = nullptr; float* Yout = nullptr;
  if constexpr (UP){
    if (e < NEXP){
      nrows = g_cnt[e]; gidx = &g_idx[e*T_TOK]; A = g_xh;
      Bp = &g_wup[(size_t)e*FDIM*DDIM]; Hc = &g_h[(size_t)e*T_TOK*FDIM];
    } else { nrows = T_TOK; A = g_xh; Bp = g_swu; Hc = g_hs; }
  } else {
    if (e < NEXP){
      nrows = g_cnt[e]; A = &g_h[(size_t)e*T_TOK*FDIM];
      Bp = &g_wdn[(size_t)e*DDIM*FDIM]; Yout = &g_yr[(size_t)e*T_TOK*DDIM];
    } else { nrows = T_TOK; A = g_hs; Bp = g_swd; Yout = gout; }
  }

  const int m0 = blockIdx.x * BM;
  if (m0 >= nrows) return;
  const int n0 = blockIdx.y * BN;

  extern __shared__ char smem[];
  const uint32_t sbase = smem_u32(smem);

  const int tid = threadIdx.x, lane = tid & 31, warp = tid >> 5;
  const int wm = (warp & 1) * 64;
  const int wn = (warp >> 1) * 64;

  const int lrow = tid >> 3, lkc = tid & 7;
  const uint32_t lsw = (uint32_t)(lrow*128 + ((lkc ^ (lrow & 7)) << 4));

  int srow[8];
#pragma unroll
  for (int j=0;j<8;j++){
    int gm = m0 + lrow + 16*j;
    int sr = gm;
    if constexpr (UP){ if (e < NEXP) sr = (gm < nrows) ? gidx[gm] : 0; }
    srow[j] = sr;
  }
  const __half* Ab  = A + lkc*8;
  const __half* bp0 = Bp + (size_t)(n0 + lrow)*KD + lkc*8;

  auto load_stage = [&](int slot, int kt){
    uint32_t sa = sbase + slot*STAGE;
    uint32_t sb = sa + BM*128;
    int k0 = kt*BK;
#pragma unroll
    for (int j=0;j<8;j++) cp16s(sa + lsw + j*16*128, Ab + (size_t)srow[j]*KD + k0);
#pragma unroll
    for (int j=0;j<8;j++) cp16s(sb + lsw + j*16*128, bp0 + (size_t)j*16*KD + k0);
    cp_commit();
  };

  float acc[4][8][4];
#pragma unroll
  for (int a=0;a<4;a++)
#pragma unroll
    for (int b=0;b<8;b++)
#pragma unroll
      for (int r=0;r<4;r++) acc[a][b][r]=0.f;

  uint32_t af[2][4][4], bf[2][8][2];
  auto load_frag = [&](int fb, uint32_t sa, uint32_t sb, int ks){
#pragma unroll
    for (int mi=0;mi<4;mi++){
      int r  = wm + mi*16 + (lane & 15);
      int kc = ks*2 + (lane >> 4);
      ldsm4(af[fb][mi], sa + r*128 + ((kc ^ (r & 7)) << 4));
    }
#pragma unroll
    for (int nj=0;nj<4;nj++){
      int g  = lane >> 3;
      int r  = wn + nj*16 + ((g >> 1) << 3) + (lane & 7);
      int kc = ks*2 + (g & 1);
      uint32_t t4[4];
      ldsm4(t4, sb + r*128 + ((kc ^ (r & 7)) << 4));
      bf[fb][nj*2  ][0]=t4[0]; bf[fb][nj*2  ][1]=t4[1];
      bf[fb][nj*2+1][0]=t4[2]; bf[fb][nj*2+1][1]=t4[3];
    }
  };

#pragma unroll
  for (int p=0;p<NST-1;p++) load_stage(p, p);

  for (int kt=0; kt<KT; ++kt){
    cp_wait<NST-2>();
    __syncthreads();

    uint32_t sa = sbase + (kt % NST)*STAGE;
    uint32_t sb = sa + BM*128;
    load_frag(0, sa, sb, 0);

    int lt = kt + NST - 1;
    if (lt < KT) load_stage(lt % NST, lt);

#pragma unroll
    for (int ks=0; ks<BK/16; ++ks){
      int cur = ks & 1;
      if (ks+1 < BK/16) load_frag(cur^1, sa, sb, ks+1);
#pragma unroll
      for (int mi=0;mi<4;mi++)
#pragma unroll
        for (int ni=0;ni<8;ni++)
          mma16816(acc[mi][ni], af[cur][mi], bf[cur][ni]);
    }
  }

  // ------------------------------- epilogue -------------------------------
  const int gr = lane >> 2, gc = (lane & 3)*2;
#pragma unroll
  for (int mi=0;mi<4;mi++){
#pragma unroll
    for (int rr=0;rr<2;rr++){
      int m = m0 + wm + mi*16 + gr + rr*8;
      if (m < nrows){
        if constexpr (UP){
          __half* dst = &Hc[(size_t)m*ND + n0 + wn];
#pragma unroll
          for (int ni=0;ni<8;ni++){
            float v0 = acc[mi][ni][rr*2+0];
            float v1 = acc[mi][ni][rr*2+1];
            v0 = v0 / (1.f + __expf(-v0));
            v1 = v1 / (1.f + __expf(-v1));
            *reinterpret_cast<__half2*>(dst + ni*8 + gc) = __floats2half2_rn(v0, v1);
          }
        } else {
          float* dst = &Yout[(size_t)m*ND + n0 + wn];
#pragma unroll
          for (int ni=0;ni<8;ni++){
            float2 f = make_float2(acc[mi][ni][rr*2+0], acc[mi][ni][rr*2+1]);
            *reinterpret_cast<float2*>(dst + ni*8 + gc) = f;
          }
        }
      }
    }
  }
}

// ------------------------------- combine -------------------------------
__global__ void combine_kernel(float* __restrict__ out){
  const int t = blockIdx.x;
  const int e0 = g_te[2*t], e1 = g_te[2*t+1];
  const int s0 = g_ts[2*t], s1 = g_ts[2*t+1];
  const float w0 = g_tw[2*t], w1 = g_tw[2*t+1];
  const float4* y0 = reinterpret_cast<const float4*>(&g_yr[((size_t)e0*T_TOK + s0)*DDIM]);
  const float4* y1 = reinterpret_cast<const float4*>(&g_yr[((size_t)e1*T_TOK + s1)*DDIM]);
  float4* o = reinterpret_cast<float4*>(out + (size_t)t*DDIM);
  const int i = threadIdx.x;
  float4 a = o[i], b = y0[i], c = y1[i];
  a.x += w0*b.x + w1*c.x;
  a.y += w0*b.y + w1*c.y;
  a.z += w0*b.z + w1*c.z;
  a.w += w0*b.w + w1*c.w;
  o[i] = a;
}

// ------------------------------- launch (multi-stream fork-join graph) -------------------------------
extern "C" void kernel_launch(void* const* d_in, const int* in_sizes, int n_in,
                              void* d_out, int out_size){
  const float* x   = (const float*)d_in[0];
  const float* rw  = (const float*)d_in[1];
  const float* rb  = (const float*)d_in[2];
  const float* wup = (const float*)d_in[3];
  const float* wdn = (const float*)d_in[4];
  const float* swu = (const float*)d_in[5];
  const float* swd = (const float*)d_in[6];
  float* out = (float*)d_out;

  void *pxh,*pwu,*pwd,*psu,*psd,*pcnt;
  cudaGetSymbolAddress(&pxh, g_xh);
  cudaGetSymbolAddress(&pwu, g_wup);
  cudaGetSymbolAddress(&pwd, g_wdn);
  cudaGetSymbolAddress(&psu, g_swu);
  cudaGetSymbolAddress(&psd, g_swd);
  cudaGetSymbolAddress(&pcnt, g_cnt);

  cudaFuncSetAttribute(moe_gemm2<0>, cudaFuncAttributeMaxDynamicSharedMemorySize, SMEM_DYN);
  cudaFuncSetAttribute(moe_gemm2<1>, cudaFuncAttributeMaxDynamicSharedMemorySize, SMEM_DYN);

  auto f2h = [](const float* s, void* d, long n4, cudaStream_t st){
    int nb = (int)((n4 + 1023) / 1024);
    f2h_kernel<<<nb, 256, 0, st>>>((const float4*)s, (uint2*)d, (int)n4);
  };

  // fork from origin stream
  cudaEventRecord(g_side.ef, 0);
  cudaStreamWaitEvent(g_side.sa, g_side.ef, 0);
  cudaStreamWaitEvent(g_side.sb, g_side.ef, 0);
  cudaStreamWaitEvent(g_side.sr, g_side.ef, 0);
  cudaStreamWaitEvent(g_side.sc, g_side.ef, 0);

  // concurrent converts + router
  f2h(x, pxh, (long)T_TOK*DDIM/4, 0);                 // stream 0: x
  cudaEventRecord(g_side.e_x, 0);
  f2h(wup, pwu, (long)NEXP*FDIM*DDIM/4, g_side.sa);   // sa: routed up weights
  cudaEventRecord(g_side.e_wu, g_side.sa);
  f2h(swu, psu, (long)FDIM*DDIM/4, g_side.sb);        // sb: shared up weights
  cudaEventRecord(g_side.e_su, g_side.sb);
  cudaMemsetAsync(pcnt, 0, NEXP*sizeof(int), g_side.sr);
  router_kernel<<<T_TOK, 256, 0, g_side.sr>>>(x, rw, rb);
  cudaEventRecord(g_side.e_r, g_side.sr);
  f2h(wdn, pwd, (long)NEXP*DDIM*FDIM/4, g_side.sc);   // sc: down weights
  f2h(swd, psd, (long)DDIM*FDIM/4, g_side.sc);
  cudaEventRecord(g_side.e_wd, g_side.sc);

  // per-expert chains: up(e) -> down(e)
  for (int e = 0; e < NCHAIN; ++e){
    cudaStream_t s = g_side.se[e];
    cudaStreamWaitEvent(s, g_side.e_x, 0);
    cudaStreamWaitEvent(s, g_side.e_r, 0);
    cudaStreamWaitEvent(s, (e < NEXP) ? g_side.e_wu : g_side.e_su, 0);
    moe_gemm2<1><<<dim3(T_TOK/BM, FDIM/BN), 128, SMEM_DYN, s>>>(out, e);
    cudaStreamWaitEvent(s, g_side.e_wd, 0);
    moe_gemm2<0><<<dim3(T_TOK/BM, DDIM/BN), 128, SMEM_DYN, s>>>(out, e);
    cudaEventRecord(g_side.e_done[e], s);
  }

  // join all chains back to origin, then combine
  for (int e = 0; e < NCHAIN; ++e)
    cudaStreamWaitEvent(0, g_side.e_done[e], 0);
  combine_kernel<<<T_TOK, 256>>>(out);
}

// round 16
// speedup vs baseline: 1.2702x; 1.0163x over previous
#include <cuda_runtime.h>
#include <cuda_fp16.h>
#include <cstdint>

#define T_TOK 4096
#define DDIM  1024
#define FDIM  2048
#define NEXP  8
#define BM 128
#define BN 128
#define BK 64
#define NST 3
#define STAGE (BM*128 + BN*128)          /* 32 KB per stage */
#define SMEM_DYN (NST*STAGE + 128)

// ------------------- static device scratch -------------------
__device__ __align__(16) __half g_xh [(size_t)T_TOK*DDIM];
__device__ __align__(16) __half g_wup[(size_t)NEXP*FDIM*DDIM];
__device__ __align__(16) __half g_wdn[(size_t)NEXP*DDIM*FDIM];
__device__ __align__(16) __half g_swu[(size_t)FDIM*DDIM];
__device__ __align__(16) __half g_swd[(size_t)DDIM*FDIM];
__device__ __align__(16) __half g_h  [(size_t)NEXP*T_TOK*FDIM];
__device__ __align__(16) __half g_hs [(size_t)T_TOK*FDIM];
__device__ __align__(16) float  g_yr [(size_t)NEXP*T_TOK*DDIM];
__device__ int   g_cnt[NEXP];
__device__ int   g_idx[NEXP*T_TOK];
__device__ int   g_te[2*T_TOK];
__device__ int   g_ts[2*T_TOK];
__device__ float g_tw[2*T_TOK];

// ------------------- pre-main streams/events (host objects only) -------------------
#define NCHAIN (NEXP+1)
struct SideInit {
  cudaStream_t sr;                     // router
  cudaStream_t se[NCHAIN];             // per-expert chains
  cudaEvent_t  ef, e_x, e_r, e_done[NCHAIN];
  SideInit(){
    cudaStreamCreateWithFlags(&sr, cudaStreamNonBlocking);
    for (int i=0;i<NCHAIN;i++) cudaStreamCreateWithFlags(&se[i], cudaStreamNonBlocking);
    cudaEventCreateWithFlags(&ef,  cudaEventDisableTiming);
    cudaEventCreateWithFlags(&e_x, cudaEventDisableTiming);
    cudaEventCreateWithFlags(&e_r, cudaEventDisableTiming);
    for (int i=0;i<NCHAIN;i++) cudaEventCreateWithFlags(&e_done[i], cudaEventDisableTiming);
  }
};
static SideInit g_side;

// ------------------------------- helpers -------------------------------
__device__ __forceinline__ uint32_t smem_u32(const void* p){
  uint32_t a;
  asm("{ .reg .u64 t; cvta.to.shared.u64 t, %1; cvt.u32.u64 %0, t; }" : "=r"(a) : "l"(p));
  return a;
}
__device__ __forceinline__ void cp16s(uint32_t sa, const void* g){
  asm volatile("cp.async.cg.shared.global [%0], [%1], 16;\n" :: "r"(sa), "l"(g));
}
__device__ __forceinline__ void cp_commit(){ asm volatile("cp.async.commit_group;\n"); }
template<int N> __device__ __forceinline__ void cp_wait(){
  asm volatile("cp.async.wait_group %0;\n" :: "n"(N));
}
__device__ __forceinline__ void ldsm4(uint32_t* r, uint32_t a){
  asm volatile("ldmatrix.sync.aligned.m8n8.x4.shared.b16 {%0,%1,%2,%3}, [%4];\n"
    : "=r"(r[0]),"=r"(r[1]),"=r"(r[2]),"=r"(r[3]) : "r"(a));
}
__device__ __forceinline__ void mma16816(float* c, const uint32_t* a, const uint32_t* b){
  asm volatile("mma.sync.aligned.m16n8k16.row.col.f32.f16.f16.f32 "
    "{%0,%1,%2,%3}, {%4,%5,%6,%7}, {%8,%9}, {%0,%1,%2,%3};\n"
    : "+f"(c[0]),"+f"(c[1]),"+f"(c[2]),"+f"(c[3])
    : "r"(a[0]),"r"(a[1]),"r"(a[2]),"r"(a[3]), "r"(b[0]),"r"(b[1]));
}

// ------------------------------- fp32 -> fp16 convert (ILP-4 streaming) -------------------------------
__global__ void f2h_kernel(const float4* __restrict__ s, uint2* __restrict__ d, int n4){
  int i0 = blockIdx.x*(blockDim.x*4) + threadIdx.x;
  float4 v[4];
#pragma unroll
  for (int u=0;u<4;u++){
    int i = i0 + u*blockDim.x;
    if (i < n4) v[u] = s[i];
  }
#pragma unroll
  for (int u=0;u<4;u++){
    int i = i0 + u*blockDim.x;
    if (i < n4){
      __half2 h0 = __floats2half2_rn(v[u].x, v[u].y);
      __half2 h1 = __floats2half2_rn(v[u].z, v[u].w);
      uint2 o;
      o.x = *reinterpret_cast<uint32_t*>(&h0);
      o.y = *reinterpret_cast<uint32_t*>(&h1);
      d[i] = o;
    }
  }
}

// ------------------------------- router: one warp = one token x all experts -------------------------------
__global__ void router_kernel(const float* __restrict__ x,
                              const float* __restrict__ rw,
                              const float* __restrict__ rb){
  const int warp = threadIdx.x >> 5, lane = threadIdx.x & 31;
  const int t = blockIdx.x*8 + warp;
  const float4* xr = reinterpret_cast<const float4*>(x + (size_t)t*DDIM);
  float4 xv[8];
#pragma unroll
  for (int i=0;i<8;i++) xv[i] = xr[lane + 32*i];
  float lg[NEXP];
#pragma unroll
  for (int e=0;e<NEXP;e++){
    const float4* wr = reinterpret_cast<const float4*>(rw + (size_t)e*DDIM);
    float acc = 0.f;
#pragma unroll
    for (int i=0;i<8;i++){
      float4 b = wr[lane + 32*i];
      acc += xv[i].x*b.x + xv[i].y*b.y + xv[i].z*b.z + xv[i].w*b.w;
    }
#pragma unroll
    for (int o=16;o;o>>=1) acc += __shfl_xor_sync(0xffffffffu, acc, o);
    lg[e] = acc + rb[e];
  }
  if (lane == 0){
    int i0=0; float v0=lg[0];
#pragma unroll
    for (int e=1;e<NEXP;e++) if (lg[e] > v0){ v0=lg[e]; i0=e; }
    int i1=-1; float v1=-3.4e38f;
#pragma unroll
    for (int e=0;e<NEXP;e++) if (e!=i0 && lg[e] > v1){ v1=lg[e]; i1=e; }
    float w0 = 1.f/(1.f + expf(v1 - v0));
    float w1 = 1.f - w0;
    int s0 = atomicAdd(&g_cnt[i0],1);
    g_idx[i0*T_TOK+s0] = t;
    int s1 = atomicAdd(&g_cnt[i1],1);
    g_idx[i1*T_TOK+s1] = t;
    g_te[2*t]=i0; g_te[2*t+1]=i1;
    g_ts[2*t]=s0; g_ts[2*t+1]=s1;
    g_tw[2*t]=w0; g_tw[2*t+1]=w1;
  }
}

// ------------------------------- grouped GEMM (R14 config; expert passed as arg) -------------------------------
template<int UP>
__global__ __launch_bounds__(128, 2)
void moe_gemm2(float* __restrict__ gout, int e){
  constexpr int KD = UP ? DDIM : FDIM;
  constexpr int ND = UP ? FDIM : DDIM;
  constexpr int KT = KD / BK;

  int nrows; const __half* A; const __half* Bp;
  const int* gidx = nullptr; __half* Hc = nullptr; float* Yout = nullptr;
  if constexpr (UP){
    if (e < NEXP){
      nrows = g_cnt[e]; gidx = &g_idx[e*T_TOK]; A = g_xh;
      Bp = &g_wup[(size_t)e*FDIM*DDIM]; Hc = &g_h[(size_t)e*T_TOK*FDIM];
    } else { nrows = T_TOK; A = g_xh; Bp = g_swu; Hc = g_hs; }
  } else {
    if (e < NEXP){
      nrows = g_cnt[e]; A = &g_h[(size_t)e*T_TOK*FDIM];
      Bp = &g_wdn[(size_t)e*DDIM*FDIM]; Yout = &g_yr[(size_t)e*T_TOK*DDIM];
    } else { nrows = T_TOK; A = g_hs; Bp = g_swd; Yout = gout; }
  }

  const int m0 = blockIdx.x * BM;
  if (m0 >= nrows) return;
  const int n0 = blockIdx.y * BN;

  extern __shared__ char smem[];
  const uint32_t sbase = smem_u32(smem);

  const int tid = threadIdx.x, lane = tid & 31, warp = tid >> 5;
  const int wm = (warp & 1) * 64;
  const int wn = (warp >> 1) * 64;

  const int lrow = tid >> 3, lkc = tid & 7;
  const uint32_t lsw = (uint32_t)(lrow*128 + ((lkc ^ (lrow & 7)) << 4));

  int srow[8];
#pragma unroll
  for (int j=0;j<8;j++){
    int gm = m0 + lrow + 16*j;
    int sr = gm;
    if constexpr (UP){ if (e < NEXP) sr = (gm < nrows) ? gidx[gm] : 0; }
    srow[j] = sr;
  }
  const __half* Ab  = A + lkc*8;
  const __half* bp0 = Bp + (size_t)(n0 + lrow)*KD + lkc*8;

  auto load_stage = [&](int slot, int kt){
    uint32_t sa = sbase + slot*STAGE;
    uint32_t sb = sa + BM*128;
    int k0 = kt*BK;
#pragma unroll
    for (int j=0;j<8;j++) cp16s(sa + lsw + j*16*128, Ab + (size_t)srow[j]*KD + k0);
#pragma unroll
    for (int j=0;j<8;j++) cp16s(sb + lsw + j*16*128, bp0 + (size_t)j*16*KD + k0);
    cp_commit();
  };

  float acc[4][8][4];
#pragma unroll
  for (int a=0;a<4;a++)
#pragma unroll
    for (int b=0;b<8;b++)
#pragma unroll
      for (int r=0;r<4;r++) acc[a][b][r]=0.f;

  uint32_t af[2][4][4], bf[2][8][2];
  auto load_frag = [&](int fb, uint32_t sa, uint32_t sb, int ks){
#pragma unroll
    for (int mi=0;mi<4;mi++){
      int r  = wm + mi*16 + (lane & 15);
      int kc = ks*2 + (lane >> 4);
      ldsm4(af[fb][mi], sa + r*128 + ((kc ^ (r & 7)) << 4));
    }
#pragma unroll
    for (int nj=0;nj<4;nj++){
      int g  = lane >> 3;
      int r  = wn + nj*16 + ((g >> 1) << 3) + (lane & 7);
      int kc = ks*2 + (g & 1);
      uint32_t t4[4];
      ldsm4(t4, sb + r*128 + ((kc ^ (r & 7)) << 4));
      bf[fb][nj*2  ][0]=t4[0]; bf[fb][nj*2  ][1]=t4[1];
      bf[fb][nj*2+1][0]=t4[2]; bf[fb][nj*2+1][1]=t4[3];
    }
  };

#pragma unroll
  for (int p=0;p<NST-1;p++) load_stage(p, p);

  for (int kt=0; kt<KT; ++kt){
    cp_wait<NST-2>();
    __syncthreads();

    uint32_t sa = sbase + (kt % NST)*STAGE;
    uint32_t sb = sa + BM*128;
    load_frag(0, sa, sb, 0);

    int lt = kt + NST - 1;
    if (lt < KT) load_stage(lt % NST, lt);

#pragma unroll
    for (int ks=0; ks<BK/16; ++ks){
      int cur = ks & 1;
      if (ks+1 < BK/16) load_frag(cur^1, sa, sb, ks+1);
#pragma unroll
      for (int mi=0;mi<4;mi++)
#pragma unroll
        for (int ni=0;ni<8;ni++)
          mma16816(acc[mi][ni], af[cur][mi], bf[cur][ni]);
    }
  }

  // ------------------------------- epilogue -------------------------------
  const int gr = lane >> 2, gc = (lane & 3)*2;
#pragma unroll
  for (int mi=0;mi<4;mi++){
#pragma unroll
    for (int rr=0;rr<2;rr++){
      int m = m0 + wm + mi*16 + gr + rr*8;
      if (m < nrows){
        if constexpr (UP){
          __half* dst = &Hc[(size_t)m*ND + n0 + wn];
#pragma unroll
          for (int ni=0;ni<8;ni++){
            float v0 = acc[mi][ni][rr*2+0];
            float v1 = acc[mi][ni][rr*2+1];
            v0 = v0 / (1.f + __expf(-v0));
            v1 = v1 / (1.f + __expf(-v1));
            *reinterpret_cast<__half2*>(dst + ni*8 + gc) = __floats2half2_rn(v0, v1);
          }
        } else {
          float* dst = &Yout[(size_t)m*ND + n0 + wn];
#pragma unroll
          for (int ni=0;ni<8;ni++){
            float2 f = make_float2(acc[mi][ni][rr*2+0], acc[mi][ni][rr*2+1]);
            *reinterpret_cast<float2*>(dst + ni*8 + gc) = f;
          }
        }
      }
    }
  }
}

// ------------------------------- combine -------------------------------
__global__ void combine_kernel(float* __restrict__ out){
  const int t = blockIdx.x;
  const int e0 = g_te[2*t], e1 = g_te[2*t+1];
  const int s0 = g_ts[2*t], s1 = g_ts[2*t+1];
  const float w0 = g_tw[2*t], w1 = g_tw[2*t+1];
  const float4* y0 = reinterpret_cast<const float4*>(&g_yr[((size_t)e0*T_TOK + s0)*DDIM]);
  const float4* y1 = reinterpret_cast<const float4*>(&g_yr[((size_t)e1*T_TOK + s1)*DDIM]);
  float4* o = reinterpret_cast<float4*>(out + (size_t)t*DDIM);
  const int i = threadIdx.x;
  float4 a = o[i], b = y0[i], c = y1[i];
  a.x += w0*b.x + w1*c.x;
  a.y += w0*b.y + w1*c.y;
  a.z += w0*b.z + w1*c.z;
  a.w += w0*b.w + w1*c.w;
  o[i] = a;
}

// ------------------------------- launch (per-expert self-contained chains) -------------------------------
extern "C" void kernel_launch(void* const* d_in, const int* in_sizes, int n_in,
                              void* d_out, int out_size){
  const float* x   = (const float*)d_in[0];
  const float* rw  = (const float*)d_in[1];
  const float* rb  = (const float*)d_in[2];
  const float* wup = (const float*)d_in[3];
  const float* wdn = (const float*)d_in[4];
  const float* swu = (const float*)d_in[5];
  const float* swd = (const float*)d_in[6];
  float* out = (float*)d_out;

  void *pxh,*pwu,*pwd,*psu,*psd,*pcnt;
  cudaGetSymbolAddress(&pxh, g_xh);
  cudaGetSymbolAddress(&pwu, g_wup);
  cudaGetSymbolAddress(&pwd, g_wdn);
  cudaGetSymbolAddress(&psu, g_swu);
  cudaGetSymbolAddress(&psd, g_swd);
  cudaGetSymbolAddress(&pcnt, g_cnt);

  cudaFuncSetAttribute(moe_gemm2<0>, cudaFuncAttributeMaxDynamicSharedMemorySize, SMEM_DYN);
  cudaFuncSetAttribute(moe_gemm2<1>, cudaFuncAttributeMaxDynamicSharedMemorySize, SMEM_DYN);

  auto f2h = [](const float* s, void* d, long n4, cudaStream_t st){
    int nb = (int)((n4 + 1023) / 1024);
    f2h_kernel<<<nb, 256, 0, st>>>((const float4*)s, (uint2*)d, (int)n4);
  };

  // fork from origin stream
  cudaEventRecord(g_side.ef, 0);
  cudaStreamWaitEvent(g_side.sr, g_side.ef, 0);
  for (int e = 0; e < NCHAIN; ++e) cudaStreamWaitEvent(g_side.se[e], g_side.ef, 0);

  // stream 0: x convert
  f2h(x, pxh, (long)T_TOK*DDIM/4, 0);
  cudaEventRecord(g_side.e_x, 0);

  // router stream
  cudaMemsetAsync(pcnt, 0, NEXP*sizeof(int), g_side.sr);
  router_kernel<<<T_TOK/8, 256, 0, g_side.sr>>>(x, rw, rb);
  cudaEventRecord(g_side.e_r, g_side.sr);

  // per-expert self-contained chains: own weight converts -> up -> down.
  // Shared expert (e=8) first: biggest work, needs no router.
  const long WUP4 = (long)FDIM*DDIM/4, WDN4 = (long)DDIM*FDIM/4;
  for (int k = 0; k < NCHAIN; ++k){
    int e = (k == 0) ? NEXP : (k - 1);
    cudaStream_t s = g_side.se[e];
    if (e < NEXP){
      f2h(wup + (size_t)e*FDIM*DDIM, (char*)pwu + (size_t)e*FDIM*DDIM*2, WUP4, s);
      f2h(wdn + (size_t)e*DDIM*FDIM, (char*)pwd + (size_t)e*DDIM*FDIM*2, WDN4, s);
    } else {
      f2h(swu, psu, WUP4, s);
      f2h(swd, psd, WDN4, s);
    }
    cudaStreamWaitEvent(s, g_side.e_x, 0);
    if (e < NEXP) cudaStreamWaitEvent(s, g_side.e_r, 0);
    moe_gemm2<1><<<dim3(T_TOK/BM, FDIM/BN), 128, SMEM_DYN, s>>>(out, e);
    moe_gemm2<0><<<dim3(T_TOK/BM, DDIM/BN), 128, SMEM_DYN, s>>>(out, e);
    cudaEventRecord(g_side.e_done[e], s);
  }

  // join all chains back to origin, then combine
  for (int e = 0; e < NCHAIN; ++e)
    cudaStreamWaitEvent(0, g_side.e_done[e], 0);
  combine_kernel<<<T_TOK, 256>>>(out);
}